// round 11
// baseline (speedup 1.0000x reference)
#include <cuda_runtime.h>
#include <cuda_bf16.h>
#include <math.h>
#include <stdint.h>

#define Bsz 4
#define Nq  8192
#define Mp  2048
#define C1  128
#define C2  256
#define CIN 384
#define CO0 256
#define CO1 128
#define NC  (Bsz*Nq)   // 32768

// ---------------- scratch (static device globals; no allocation) ----------------
__device__ float g_p2T[Bsz*Mp*C2];                       // points2^T (B,M,C2) fp32
__device__ __nv_bfloat16 g_Xhi[(size_t)NC*CIN];          // X hi split [col][k]
__device__ __nv_bfloat16 g_Xlo[(size_t)NC*CIN];          // X lo split [col][k]
__device__ __nv_bfloat16 g_W0h[CO0*CIN], g_W0l[CO0*CIN];
__device__ __nv_bfloat16 g_W1h[CO1*CO0], g_W1l[CO1*CO0];
__device__ float g_Y0T[(size_t)NC*CO0];                  // conv0 out [pt][ch] fp32
__device__ float g_p0s[512*CO0], g_p0q[512*CO0];         // bn0 partials
__device__ float g_scale0[CO0], g_shift0[CO0];
__device__ float g_scale1[CO1], g_shift1[CO1];

// ---------------- helpers --------------------------------------------------------
__device__ __forceinline__ uint32_t smem_u32(const void* p) {
    uint32_t a;
    asm("{ .reg .u64 t; cvta.to.shared.u64 t, %1; cvt.u32.u64 %0, t; }" : "=r"(a) : "l"(p));
    return a;
}

#define LDSM4(r, addr) \
    asm volatile("ldmatrix.sync.aligned.m8n8.x4.shared.b16 {%0,%1,%2,%3}, [%4];" \
        : "=r"((r)[0]),"=r"((r)[1]),"=r"((r)[2]),"=r"((r)[3]) : "r"(addr))

__device__ __forceinline__ void mma_bf16(float* d, const uint32_t* a, const uint32_t* b) {
    asm volatile("mma.sync.aligned.m16n8k16.row.col.f32.bf16.bf16.f32 "
        "{%0,%1,%2,%3}, {%4,%5,%6,%7}, {%8,%9}, {%0,%1,%2,%3};"
        : "+f"(d[0]), "+f"(d[1]), "+f"(d[2]), "+f"(d[3])
        : "r"(a[0]), "r"(a[1]), "r"(a[2]), "r"(a[3]), "r"(b[0]), "r"(b[1]));
}

__device__ __forceinline__ void split_bf(float v, unsigned short& h, unsigned short& l) {
    __nv_bfloat16 hb = __float2bfloat16(v);
    float hf = __bfloat162float(hb);
    __nv_bfloat16 lb = __float2bfloat16(v - hf);
    union { __nv_bfloat16 b; unsigned short u; } ch, cl;
    ch.b = hb; cl.b = lb;
    h = ch.u; l = cl.u;
}

__device__ __forceinline__ void split8(const float* v, uint4& h4, uint4& l4) {
    unsigned short h[8], l[8];
#pragma unroll
    for (int i = 0; i < 8; i++) split_bf(v[i], h[i], l[i]);
    h4 = make_uint4((uint32_t)h[0]|((uint32_t)h[1]<<16), (uint32_t)h[2]|((uint32_t)h[3]<<16),
                    (uint32_t)h[4]|((uint32_t)h[5]<<16), (uint32_t)h[6]|((uint32_t)h[7]<<16));
    l4 = make_uint4((uint32_t)l[0]|((uint32_t)l[1]<<16), (uint32_t)l[2]|((uint32_t)l[3]<<16),
                    (uint32_t)l[4]|((uint32_t)l[5]<<16), (uint32_t)l[6]|((uint32_t)l[7]<<16));
}

// branchless top-3 insert (strict <, ties keep earlier candidate)
__device__ __forceinline__ void top3_insert(float d2, int m,
    float& d0, float& d1, float& d2_, int& i0, int& i1, int& i2)
{
    bool c0 = d2 < d0;
    bool c1 = d2 < d1;
    bool c2 = d2 < d2_;
    d2_ = c1 ? d1 : (c2 ? d2 : d2_);
    i2  = c1 ? i1 : (c2 ? m  : i2);
    d1  = c0 ? d0 : (c1 ? d2 : d1);
    i1  = c0 ? i0 : (c1 ? m  : i1);
    d0  = c0 ? d2 : d0;
    i0  = c0 ? m  : i0;
}

// ---------------- weight presplit ------------------------------------------------
__global__ void splitw_kernel(const float* __restrict__ W0, const float* __restrict__ W1)
{
    int i = blockIdx.x * 256 + threadIdx.x;
    if (i < CO0*CIN) {
        unsigned short h, l; split_bf(W0[i], h, l);
        union { __nv_bfloat16 b; unsigned short u; } ch, cl; ch.u = h; cl.u = l;
        g_W0h[i] = ch.b; g_W0l[i] = cl.b;
    }
    int j = i - CO0*CIN;
    if (j >= 0 && j < CO1*CO0) {
        unsigned short h, l; split_bf(W1[j], h, l);
        union { __nv_bfloat16 b; unsigned short u; } ch, cl; ch.u = h; cl.u = l;
        g_W1h[j] = ch.b; g_W1l[j] = cl.b;
    }
}

// ---------------- transpose (fp32): in (B,R,C) -> out[(b*C+c)*ostride + r] -------
__global__ void transpose_kernel(const float* __restrict__ in, float* __restrict__ out,
                                 int R, int C, int ostride)
{
    __shared__ float tile[32][33];
    int b  = blockIdx.z;
    int c0 = blockIdx.x * 32;
    int r0 = blockIdx.y * 32;
    const float* ip = in + (size_t)b * R * C;
#pragma unroll
    for (int s = 0; s < 4; s++) {
        int r = r0 + threadIdx.y + 8*s;
        tile[threadIdx.y + 8*s][threadIdx.x] = ip[(size_t)r * C + c0 + threadIdx.x];
    }
    __syncthreads();
#pragma unroll
    for (int s = 0; s < 4; s++) {
        int c = c0 + threadIdx.y + 8*s;
        out[((size_t)b * C + c) * ostride + r0 + threadIdx.x] = tile[threadIdx.x][threadIdx.y + 8*s];
    }
}

// ---------------- transpose points1 -> split bf16 into g_Xhi/lo [col][256+r] ----
__global__ void transpose_split_kernel(const float* __restrict__ in)
{
    __shared__ float tile[32][33];
    int b  = blockIdx.z;
    int c0 = blockIdx.x * 32;   // point
    int r0 = blockIdx.y * 32;   // channel
    const float* ip = in + (size_t)b * C1 * Nq;
#pragma unroll
    for (int s = 0; s < 4; s++) {
        int r = r0 + threadIdx.y + 8*s;
        tile[threadIdx.y + 8*s][threadIdx.x] = ip[(size_t)r * Nq + c0 + threadIdx.x];
    }
    __syncthreads();
#pragma unroll
    for (int s = 0; s < 4; s++) {
        int c = c0 + threadIdx.y + 8*s;
        float v = tile[threadIdx.x][threadIdx.y + 8*s];
        unsigned short h, l;
        split_bf(v, h, l);
        size_t idx = ((size_t)b * Nq + c) * CIN + C2 + r0 + threadIdx.x;
        union { __nv_bfloat16 b16; unsigned short u; } cvh, cvl;
        cvh.u = h; cvl.u = l;
        g_Xhi[idx] = cvh.b16;
        g_Xlo[idx] = cvl.b16;
    }
}

// ---------------- 3-NN + weights + interpolation (branchless chunked scan) ------
// Block: 64 queries, 512 threads = 8 chunk-groups of 64. Each thread scans a
// 256-ref chunk branchlessly; 24 candidates merged in chunk-then-rank order
// (strict <, reproducing the sequential scan's tie semantics).
#define KQ   64
#define KCH  8
#define KCHLEN (Mp/KCH)   // 256

__global__ __launch_bounds__(512) void knn_interp_kernel(
    const float* __restrict__ xyz1, const float* __restrict__ xyz2,
    const float* __restrict__ norm1, const float* __restrict__ norm2)
{
    __shared__ float4 sp[Mp];             // 32 KB
    __shared__ float  cd[3*KCH][KQ];      // 6 KB
    __shared__ int    ci[3*KCH][KQ];      // 6 KB
    __shared__ float  sw[3][KQ];
    __shared__ int    si[3][KQ];

    int b = blockIdx.y;
    int t = threadIdx.x;
    int qi = t & (KQ-1), c = t >> 6;

    const float* x2 = xyz2 + (size_t)b * 3 * Mp;
    for (int m = t; m < Mp; m += 512) {
        float a = x2[m], e = x2[Mp + m], d = x2[2*Mp + m];
        float4 v; v.x = a; v.y = e; v.z = d; v.w = a*a + e*e + d*d;
        sp[m] = v;
    }
    __syncthreads();

    int n = blockIdx.x * KQ + qi;
    const float* x1 = xyz1 + (size_t)b * 3 * Nq;
    float qx = x1[n], qy = x1[Nq + n], qz = x1[2*Nq + n];
    float qq = qx*qx + qy*qy + qz*qz;

    float d2_0 = 1e30f, d2_1 = 1e30f, d2_2 = 1e30f;
    int   i0 = 0, i1 = 0, i2 = 0;
    int mbase = c * KCHLEN;
#pragma unroll 4
    for (int mm = 0; mm < KCHLEN; mm++) {
        int m = mbase + mm;
        float4 P = sp[m];
        float dot = qx*P.x + qy*P.y + qz*P.z;
        float d2  = qq + P.w - 2.0f*dot;       // matches reference's expanded form
        top3_insert(d2, m, d2_0, d2_1, d2_2, i0, i1, i2);
    }
    cd[c*3+0][qi] = d2_0; ci[c*3+0][qi] = i0;
    cd[c*3+1][qi] = d2_1; ci[c*3+1][qi] = i1;
    cd[c*3+2][qi] = d2_2; ci[c*3+2][qi] = i2;
    __syncthreads();

    if (c == 0) {
        float b0 = 1e30f, b1 = 1e30f, b2 = 1e30f;
        int   j0 = 0, j1 = 0, j2 = 0;
#pragma unroll
        for (int r = 0; r < 3*KCH; r++) {
            top3_insert(cd[r][qi], ci[r][qi], b0, b1, b2, j0, j1, j2);
        }
        float dist0 = sqrtf(fmaxf(b0, 1e-20f));
        float dist1 = sqrtf(fmaxf(b1, 1e-20f));
        float dist2 = sqrtf(fmaxf(b2, 1e-20f));

        const float* n1 = norm1 + (size_t)b * 3 * Nq;
        const float* n2 = norm2 + (size_t)b * 3 * Mp;
        float ax = n1[n], ay = n1[Nq+n], az = n1[2*Nq+n];
        float dx, dy, dz;
        dx = ax - n2[j0]; dy = ay - n2[Mp+j0]; dz = az - n2[2*Mp+j0];
        float nd0 = sqrtf(dx*dx + dy*dy + dz*dz);
        dx = ax - n2[j1]; dy = ay - n2[Mp+j1]; dz = az - n2[2*Mp+j1];
        float nd1 = sqrtf(dx*dx + dy*dy + dz*dz);
        dx = ax - n2[j2]; dy = ay - n2[Mp+j2]; dz = az - n2[2*Mp+j2];
        float nd2 = sqrtf(dx*dx + dy*dy + dz*dz);

        float r0 = 1.0f / fmaxf(dist0, 1e-10f);
        float r1 = 1.0f / fmaxf(dist1, 1e-10f);
        float r2 = 1.0f / fmaxf(dist2, 1e-10f);
        float rs = r0 + r1 + r2;
        float s0 = 1.0f / fmaxf(nd0, 1e-10f);
        float s1 = 1.0f / fmaxf(nd1, 1e-10f);
        float s2 = 1.0f / fmaxf(nd2, 1e-10f);
        float ssum = s0 + s1 + s2;
        sw[0][qi] = (r0 / rs) * (s0 / ssum);
        sw[1][qi] = (r1 / rs) * (s1 / ssum);
        sw[2][qi] = (r2 / rs) * (s2 / ssum);
        si[0][qi] = j0; si[1][qi] = j1; si[2][qi] = j2;
    }
    __syncthreads();

    // gather: 8 threads per query, 32 channels each
    float w0 = sw[0][qi], w1 = sw[1][qi], w2 = sw[2][qi];
    int   j0 = si[0][qi], j1 = si[1][qi], j2 = si[2][qi];
    size_t col = (size_t)b * Nq + n;
    int ch0 = c * 32;
    const float4* p0 = (const float4*)(g_p2T + ((size_t)b*Mp + j0) * C2 + ch0);
    const float4* p1 = (const float4*)(g_p2T + ((size_t)b*Mp + j1) * C2 + ch0);
    const float4* p2 = (const float4*)(g_p2T + ((size_t)b*Mp + j2) * C2 + ch0);
    uint2* xh = (uint2*)(g_Xhi + col * CIN + ch0);
    uint2* xl = (uint2*)(g_Xlo + col * CIN + ch0);
#pragma unroll
    for (int cc = 0; cc < 8; cc++) {
        float4 a = p0[cc], bq = p1[cc], cq = p2[cc];
        float r[4];
        r[0] = w0*a.x + w1*bq.x + w2*cq.x;
        r[1] = w0*a.y + w1*bq.y + w2*cq.y;
        r[2] = w0*a.z + w1*bq.z + w2*cq.z;
        r[3] = w0*a.w + w1*bq.w + w2*cq.w;
        unsigned short h[4], l[4];
#pragma unroll
        for (int j = 0; j < 4; j++) split_bf(r[j], h[j], l[j]);
        xh[cc] = make_uint2((uint32_t)h[0] | ((uint32_t)h[1]<<16),
                            (uint32_t)h[2] | ((uint32_t)h[3]<<16));
        xl[cc] = make_uint2((uint32_t)l[0] | ((uint32_t)l[1]<<16),
                            (uint32_t)l[2] | ((uint32_t)l[3]<<16));
    }
}

// ---------------- GEMM0 (mma.sync bf16x3): D[ch 128][pt 128] --------------------
#define SMA_H 0
#define SMA_L 16384
#define SMB_H 32768
#define SMB_L 49152
#define G0_SMEM (128*132*4)     // 67584

__global__ __launch_bounds__(256, 1) void gemm0_mma_kernel(const float* __restrict__ bias)
{
    extern __shared__ char sm[];
    uint32_t smb = smem_u32(sm);
    int t = threadIdx.x, lid = t & 31, wid = t >> 5;
    int wm = wid >> 2, wn = wid & 3;          // warps 2(m) x 4(n)
    int c0 = blockIdx.x * 128;                // point tile
    int m0 = blockIdx.y * 128;                // channel tile
    int sub = lid >> 3, rr = lid & 7;

    float acc[4][4][4];
#pragma unroll
    for (int i = 0; i < 4; i++)
#pragma unroll
        for (int j = 0; j < 4; j++)
#pragma unroll
            for (int q = 0; q < 4; q++) acc[i][j][q] = 0.f;

    for (int ck = 0; ck < 6; ck++) {
        int kk = ck * 64;
        __syncthreads();
        for (int i = t; i < 128*8; i += 256) {
            int r = i >> 3, j = i & 7;
            uint32_t so = (uint32_t)(r*128 + ((j ^ (r & 7)) << 4));
            *(uint4*)(sm + SMA_H + so) = *(const uint4*)(g_W0h + (size_t)(m0 + r)*CIN + kk + j*8);
            *(uint4*)(sm + SMA_L + so) = *(const uint4*)(g_W0l + (size_t)(m0 + r)*CIN + kk + j*8);
            *(uint4*)(sm + SMB_H + so) = *(const uint4*)(g_Xhi + (size_t)(c0 + r)*CIN + kk + j*8);
            *(uint4*)(sm + SMB_L + so) = *(const uint4*)(g_Xlo + (size_t)(c0 + r)*CIN + kk + j*8);
        }
        __syncthreads();
#pragma unroll
        for (int kb = 0; kb < 4; kb++) {
            int chnk = kb*2 + (sub >> 1);
            uint32_t Ah[4][4], Al[4][4], Bh[4][2], Bl[4][2];
#pragma unroll
            for (int i = 0; i < 4; i++) {
                int row = wm*64 + i*16 + ((sub & 1) << 3) + rr;
                uint32_t so = (uint32_t)(row*128 + ((chnk ^ rr) << 4));
                LDSM4(Ah[i], smb + SMA_H + so);
                LDSM4(Al[i], smb + SMA_L + so);
            }
#pragma unroll
            for (int jj = 0; jj < 2; jj++) {
                int row = wn*32 + jj*16 + ((sub & 1) << 3) + rr;
                uint32_t so = (uint32_t)(row*128 + ((chnk ^ rr) << 4));
                uint32_t rg[4];
                LDSM4(rg, smb + SMB_H + so);
                Bh[jj*2][0] = rg[0]; Bh[jj*2+1][0] = rg[1];
                Bh[jj*2][1] = rg[2]; Bh[jj*2+1][1] = rg[3];
                LDSM4(rg, smb + SMB_L + so);
                Bl[jj*2][0] = rg[0]; Bl[jj*2+1][0] = rg[1];
                Bl[jj*2][1] = rg[2]; Bl[jj*2+1][1] = rg[3];
            }
#pragma unroll
            for (int i = 0; i < 4; i++)
#pragma unroll
                for (int jt = 0; jt < 4; jt++) {
                    mma_bf16(acc[i][jt], Ah[i], Bh[jt]);
                    mma_bf16(acc[i][jt], Ah[i], Bl[jt]);
                    mma_bf16(acc[i][jt], Al[i], Bh[jt]);
                }
        }
    }

    // epilogue: transpose through smem -> g_Y0T [pt][ch], bn0 partials
    __syncthreads();
    float* s32 = (float*)sm;
#pragma unroll
    for (int i = 0; i < 4; i++) {
        int chr = wm*64 + i*16 + (lid >> 2);
#pragma unroll
        for (int jt = 0; jt < 4; jt++) {
            int pt = wn*32 + jt*8 + (lid & 3)*2;
            s32[(size_t)pt*132 + chr]       = acc[i][jt][0];
            s32[(size_t)(pt+1)*132 + chr]   = acc[i][jt][1];
            s32[(size_t)pt*132 + chr + 8]   = acc[i][jt][2];
            s32[(size_t)(pt+1)*132 + chr+8] = acc[i][jt][3];
        }
    }
    __syncthreads();
    int chn = t & 127, half = t >> 7;
    float bi = bias[m0 + chn];
    float s = 0.f, q = 0.f;
    for (int p = half*64; p < half*64 + 64; p++) {
        float v = s32[(size_t)p*132 + chn] + bi;
        s += v; q += v*v;
        g_Y0T[(size_t)(c0 + p)*CO0 + m0 + chn] = v;
    }
    g_p0s[(size_t)(blockIdx.x*2 + half)*CO0 + m0 + chn] = s;
    g_p0q[(size_t)(blockIdx.x*2 + half)*CO0 + m0 + chn] = q;
}

// ---------------- bn0 partial reduce -> scale0/shift0 ---------------------------
__global__ __launch_bounds__(256) void reduce0_kernel(const float* __restrict__ g,
                                                      const float* __restrict__ be)
{
    int chn = blockIdx.x, t = threadIdx.x;
    double s = (double)g_p0s[(size_t)t*CO0 + chn] + (double)g_p0s[(size_t)(t+256)*CO0 + chn];
    double q = (double)g_p0q[(size_t)t*CO0 + chn] + (double)g_p0q[(size_t)(t+256)*CO0 + chn];
    __shared__ double ss[256], qq[256];
    ss[t] = s; qq[t] = q;
    __syncthreads();
    for (int st = 128; st > 0; st >>= 1) {
        if (t < st) { ss[t] += ss[t+st]; qq[t] += qq[t+st]; }
        __syncthreads();
    }
    if (t == 0) {
        double inv = 1.0 / (double)NC;
        double mean = ss[0] * inv;
        double var  = qq[0] * inv - mean*mean;
        double sc   = (double)g[chn] / sqrt(var + 1e-5);
        g_scale0[chn] = (float)sc;
        g_shift0[chn] = (float)((double)be[chn] - mean * sc);
    }
}

// ---------------- GEMM1 (mma.sync bf16x3): D[ch 128][pt 128] -> d_out -----------
#define G1_SMEM (65536 + 2048)

__global__ __launch_bounds__(256, 1) void gemm1_mma_kernel(const float* __restrict__ bias,
                                                           float* __restrict__ out)
{
    extern __shared__ char sm[];
    uint32_t smb = smem_u32(sm);
    float* s_sc = (float*)(sm + 65536);
    float* s_sh = (float*)(sm + 65536 + 1024);
    int t = threadIdx.x, lid = t & 31, wid = t >> 5;
    int wm = wid >> 2, wn = wid & 3;
    int p0 = blockIdx.x * 128;
    int sub = lid >> 3, rr = lid & 7;

    s_sc[t] = g_scale0[t];
    s_sh[t] = g_shift0[t];

    float acc[4][4][4];
#pragma unroll
    for (int i = 0; i < 4; i++)
#pragma unroll
        for (int j = 0; j < 4; j++)
#pragma unroll
            for (int q = 0; q < 4; q++) acc[i][j][q] = 0.f;

    for (int ck = 0; ck < 4; ck++) {
        int kk = ck * 64;
        __syncthreads();
        for (int i = t; i < 128*8; i += 256) {
            int r = i >> 3, j = i & 7;
            uint32_t so = (uint32_t)(r*128 + ((j ^ (r & 7)) << 4));
            *(uint4*)(sm + SMA_H + so) = *(const uint4*)(g_W1h + (size_t)r*CO0 + kk + j*8);
            *(uint4*)(sm + SMA_L + so) = *(const uint4*)(g_W1l + (size_t)r*CO0 + kk + j*8);
            const float* yp = g_Y0T + (size_t)(p0 + r)*CO0 + kk + j*8;
            float v[8];
#pragma unroll
            for (int q = 0; q < 8; q++) {
                int k = kk + j*8 + q;
                v[q] = fmaxf(0.f, fmaf(yp[q], s_sc[k], s_sh[k]));
            }
            uint4 h4, l4;
            split8(v, h4, l4);
            *(uint4*)(sm + SMB_H + so) = h4;
            *(uint4*)(sm + SMB_L + so) = l4;
        }
        __syncthreads();
#pragma unroll
        for (int kb = 0; kb < 4; kb++) {
            int chnk = kb*2 + (sub >> 1);
            uint32_t Ah[4][4], Al[4][4], Bh[4][2], Bl[4][2];
#pragma unroll
            for (int i = 0; i < 4; i++) {
                int row = wm*64 + i*16 + ((sub & 1) << 3) + rr;
                uint32_t so = (uint32_t)(row*128 + ((chnk ^ rr) << 4));
                LDSM4(Ah[i], smb + SMA_H + so);
                LDSM4(Al[i], smb + SMA_L + so);
            }
#pragma unroll
            for (int jj = 0; jj < 2; jj++) {
                int row = wn*32 + jj*16 + ((sub & 1) << 3) + rr;
                uint32_t so = (uint32_t)(row*128 + ((chnk ^ rr) << 4));
                uint32_t rg[4];
                LDSM4(rg, smb + SMB_H + so);
                Bh[jj*2][0] = rg[0]; Bh[jj*2+1][0] = rg[1];
                Bh[jj*2][1] = rg[2]; Bh[jj*2+1][1] = rg[3];
                LDSM4(rg, smb + SMB_L + so);
                Bl[jj*2][0] = rg[0]; Bl[jj*2+1][0] = rg[1];
                Bl[jj*2][1] = rg[2]; Bl[jj*2+1][1] = rg[3];
            }
#pragma unroll
            for (int i = 0; i < 4; i++)
#pragma unroll
                for (int jt = 0; jt < 4; jt++) {
                    mma_bf16(acc[i][jt], Ah[i], Bh[jt]);
                    mma_bf16(acc[i][jt], Ah[i], Bl[jt]);
                    mma_bf16(acc[i][jt], Al[i], Bh[jt]);
                }
        }
    }

#pragma unroll
    for (int i = 0; i < 4; i++) {
        int ch = wm*64 + i*16 + (lid >> 2);
        float b0v = bias[ch], b8v = bias[ch + 8];
#pragma unroll
        for (int jt = 0; jt < 4; jt++) {
            int ptl = wn*32 + jt*8 + (lid & 3)*2;
            int gp = p0 + ptl;
            int b = gp >> 13, n = gp & (Nq - 1);
            float2 v0 = make_float2(acc[i][jt][0] + b0v, acc[i][jt][1] + b0v);
            float2 v1 = make_float2(acc[i][jt][2] + b8v, acc[i][jt][3] + b8v);
            *(float2*)(out + ((size_t)b*CO1 + ch)*Nq + n)     = v0;
            *(float2*)(out + ((size_t)b*CO1 + ch + 8)*Nq + n) = v1;
        }
    }
}

// ---------------- per-channel BN stats (bn1 over d_out) -------------------------
__global__ __launch_bounds__(256) void stats_kernel(const float* __restrict__ Y,
    const float* __restrict__ g, const float* __restrict__ be,
    float* __restrict__ scale, float* __restrict__ shift,
    long long chan_stride, int nchunks, long long chunk_stride, int chunk_len, float inv_count)
{
    int o = blockIdx.x;
    int tid = threadIdx.x;
    float s = 0.f, q = 0.f;
    for (int cb = 0; cb < nchunks; cb++) {
        const float4* p = (const float4*)(Y + (size_t)o * chan_stride + (size_t)cb * chunk_stride);
        int len4 = chunk_len >> 2;
        for (int i = tid; i < len4; i += 256) {
            float4 v = p[i];
            s += (v.x + v.y) + (v.z + v.w);
            q += (v.x*v.x + v.y*v.y) + (v.z*v.z + v.w*v.w);
        }
    }
    __shared__ double ss[256], sq[256];
    ss[tid] = (double)s; sq[tid] = (double)q;
    __syncthreads();
    for (int st = 128; st > 0; st >>= 1) {
        if (tid < st) { ss[tid] += ss[tid+st]; sq[tid] += sq[tid+st]; }
        __syncthreads();
    }
    if (tid == 0) {
        double mean = ss[0] * (double)inv_count;
        double var  = sq[0] * (double)inv_count - mean*mean;
        double sc   = (double)g[o] / sqrt(var + 1e-5);
        scale[o] = (float)sc;
        shift[o] = (float)((double)be[o] - mean * sc);
    }
}

// ---------------- final BN + ReLU, in place on d_out ----------------------------
__global__ __launch_bounds__(256) void bnrelu_kernel(float* __restrict__ out)
{
    int i = blockIdx.x * 256 + threadIdx.x;
    int o = (i >> 11) & 127;
    float sc = g_scale1[o], sh = g_shift1[o];
    float4* p = (float4*)out;
    float4 v = p[i];
    v.x = fmaxf(0.f, fmaf(v.x, sc, sh));
    v.y = fmaxf(0.f, fmaf(v.y, sc, sh));
    v.z = fmaxf(0.f, fmaf(v.z, sc, sh));
    v.w = fmaxf(0.f, fmaf(v.w, sc, sh));
    p[i] = v;
}

// ---------------- launch ---------------------------------------------------------
extern "C" void kernel_launch(void* const* d_in, const int* in_sizes, int n_in,
                              void* d_out, int out_size)
{
    const float* xyz1    = (const float*)d_in[0];
    const float* xyz2    = (const float*)d_in[1];
    const float* norm1   = (const float*)d_in[2];
    const float* norm2   = (const float*)d_in[3];
    const float* points1 = (const float*)d_in[4];
    const float* points2 = (const float*)d_in[5];
    const float* W0      = (const float*)d_in[6];
    const float* b0      = (const float*)d_in[7];
    const float* g0      = (const float*)d_in[8];
    const float* be0     = (const float*)d_in[9];
    const float* W1      = (const float*)d_in[10];
    const float* b1      = (const float*)d_in[11];
    const float* g1      = (const float*)d_in[12];
    const float* be1     = (const float*)d_in[13];
    float* out = (float*)d_out;

    cudaFuncSetAttribute(gemm0_mma_kernel, cudaFuncAttributeMaxDynamicSharedMemorySize, G0_SMEM);
    cudaFuncSetAttribute(gemm1_mma_kernel, cudaFuncAttributeMaxDynamicSharedMemorySize, G1_SMEM);

    float *p2T_ptr, *sc1, *sh1;
    cudaGetSymbolAddress((void**)&p2T_ptr, g_p2T);
    cudaGetSymbolAddress((void**)&sc1, g_scale1);
    cudaGetSymbolAddress((void**)&sh1, g_shift1);

    // weight presplit (bf16 hi/lo)
    splitw_kernel<<<(CO0*CIN + CO1*CO0 + 255)/256, 256>>>(W0, W1);
    // points2 (B,256,2048) -> g_p2T (B,2048,256) fp32
    transpose_kernel<<<dim3(Mp/32, C2/32, Bsz), dim3(32,8)>>>(points2, p2T_ptr, C2, Mp, C2);
    // points1 -> split bf16 into g_Xhi/lo [col][256..383]
    transpose_split_kernel<<<dim3(Nq/32, C1/32, Bsz), dim3(32,8)>>>(points1);
    // 3-NN + interpolation -> g_Xhi/lo [col][0..255]
    knn_interp_kernel<<<dim3(Nq/KQ, Bsz), 512>>>(xyz1, xyz2, norm1, norm2);
    // conv0 (HMMA bf16x3) -> g_Y0T [pt][ch] + bn0 partials
    gemm0_mma_kernel<<<dim3(NC/128, CO0/128), 256, G0_SMEM>>>(b0);
    // bn0 affine
    reduce0_kernel<<<CO0, 256>>>(g0, be0);
    // conv1 (HMMA bf16x3, bn0+relu fused in staging) -> d_out raw
    gemm1_mma_kernel<<<dim3(NC/128), 256, G1_SMEM>>>(b1, out);
    // bn1 stats over d_out raw
    stats_kernel<<<CO1, 256>>>(out, g1, be1, sc1, sh1,
                               (long long)Nq, Bsz, (long long)(CO1*Nq), Nq, 1.0f/(float)NC);
    // final bn1 + relu in place
    bnrelu_kernel<<<(Bsz*CO1*Nq/4)/256, 256>>>(out);
}

// round 12
// speedup vs baseline: 1.0537x; 1.0537x over previous
#include <cuda_runtime.h>
#include <cuda_bf16.h>
#include <math.h>
#include <stdint.h>

#define Bsz 4
#define Nq  8192
#define Mp  2048
#define C1  128
#define C2  256
#define CIN 384
#define CO0 256
#define CO1 128
#define NC  (Bsz*Nq)   // 32768

// ---------------- scratch (static device globals; no allocation) ----------------
__device__ float g_p2T[Bsz*Mp*C2];                       // points2^T (B,M,C2) fp32
__device__ __nv_bfloat16 g_Xhi[(size_t)NC*CIN];          // X hi split [col][k]
__device__ __nv_bfloat16 g_Xlo[(size_t)NC*CIN];          // X lo split [col][k]
__device__ __nv_bfloat16 g_W0h[CO0*CIN], g_W0l[CO0*CIN];
__device__ __nv_bfloat16 g_W1h[CO1*CO0], g_W1l[CO1*CO0];
__device__ float g_Y0T[(size_t)NC*CO0];                  // conv0 out [pt][ch] fp32
__device__ float g_p0s[512*CO0], g_p0q[512*CO0];         // bn0 partials
__device__ float g_scale0[CO0], g_shift0[CO0];
__device__ float g_scale1[CO1], g_shift1[CO1];

// ---------------- helpers --------------------------------------------------------
__device__ __forceinline__ uint32_t smem_u32(const void* p) {
    uint32_t a;
    asm("{ .reg .u64 t; cvta.to.shared.u64 t, %1; cvt.u32.u64 %0, t; }" : "=r"(a) : "l"(p));
    return a;
}

#define LDSM4(r, addr) \
    asm volatile("ldmatrix.sync.aligned.m8n8.x4.shared.b16 {%0,%1,%2,%3}, [%4];" \
        : "=r"((r)[0]),"=r"((r)[1]),"=r"((r)[2]),"=r"((r)[3]) : "r"(addr))

__device__ __forceinline__ void mma_bf16(float* d, const uint32_t* a, const uint32_t* b) {
    asm volatile("mma.sync.aligned.m16n8k16.row.col.f32.bf16.bf16.f32 "
        "{%0,%1,%2,%3}, {%4,%5,%6,%7}, {%8,%9}, {%0,%1,%2,%3};"
        : "+f"(d[0]), "+f"(d[1]), "+f"(d[2]), "+f"(d[3])
        : "r"(a[0]), "r"(a[1]), "r"(a[2]), "r"(a[3]), "r"(b[0]), "r"(b[1]));
}

__device__ __forceinline__ void split_bf(float v, unsigned short& h, unsigned short& l) {
    __nv_bfloat16 hb = __float2bfloat16(v);
    float hf = __bfloat162float(hb);
    __nv_bfloat16 lb = __float2bfloat16(v - hf);
    union { __nv_bfloat16 b; unsigned short u; } ch, cl;
    ch.b = hb; cl.b = lb;
    h = ch.u; l = cl.u;
}

__device__ __forceinline__ void split8(const float* v, uint4& h4, uint4& l4) {
    unsigned short h[8], l[8];
#pragma unroll
    for (int i = 0; i < 8; i++) split_bf(v[i], h[i], l[i]);
    h4 = make_uint4((uint32_t)h[0]|((uint32_t)h[1]<<16), (uint32_t)h[2]|((uint32_t)h[3]<<16),
                    (uint32_t)h[4]|((uint32_t)h[5]<<16), (uint32_t)h[6]|((uint32_t)h[7]<<16));
    l4 = make_uint4((uint32_t)l[0]|((uint32_t)l[1]<<16), (uint32_t)l[2]|((uint32_t)l[3]<<16),
                    (uint32_t)l[4]|((uint32_t)l[5]<<16), (uint32_t)l[6]|((uint32_t)l[7]<<16));
}

// sequential top-3 insert (strict <, ties keep earlier candidate) — short arms,
// ptxas predicates these (no heavy BSSY)
__device__ __forceinline__ void top3_seq(float d2, int m,
    float& d0, float& d1, float& d2_, int& i0, int& i1, int& i2)
{
    if (d2 < d2_) {
        if (d2 < d1) {
            d2_ = d1; i2 = i1;
            if (d2 < d0) { d1 = d0; i1 = i0; d0 = d2; i0 = m; }
            else         { d1 = d2; i1 = m; }
        } else { d2_ = d2; i2 = m; }
    }
}

// ---------------- weight presplit ------------------------------------------------
__global__ void splitw_kernel(const float* __restrict__ W0, const float* __restrict__ W1)
{
    int i = blockIdx.x * 256 + threadIdx.x;
    if (i < CO0*CIN) {
        unsigned short h, l; split_bf(W0[i], h, l);
        union { __nv_bfloat16 b; unsigned short u; } ch, cl; ch.u = h; cl.u = l;
        g_W0h[i] = ch.b; g_W0l[i] = cl.b;
    }
    int j = i - CO0*CIN;
    if (j >= 0 && j < CO1*CO0) {
        unsigned short h, l; split_bf(W1[j], h, l);
        union { __nv_bfloat16 b; unsigned short u; } ch, cl; ch.u = h; cl.u = l;
        g_W1h[j] = ch.b; g_W1l[j] = cl.b;
    }
}

// ---------------- transpose (fp32): in (B,R,C) -> out[(b*C+c)*ostride + r] -------
__global__ void transpose_kernel(const float* __restrict__ in, float* __restrict__ out,
                                 int R, int C, int ostride)
{
    __shared__ float tile[32][33];
    int b  = blockIdx.z;
    int c0 = blockIdx.x * 32;
    int r0 = blockIdx.y * 32;
    const float* ip = in + (size_t)b * R * C;
#pragma unroll
    for (int s = 0; s < 4; s++) {
        int r = r0 + threadIdx.y + 8*s;
        tile[threadIdx.y + 8*s][threadIdx.x] = ip[(size_t)r * C + c0 + threadIdx.x];
    }
    __syncthreads();
#pragma unroll
    for (int s = 0; s < 4; s++) {
        int c = c0 + threadIdx.y + 8*s;
        out[((size_t)b * C + c) * ostride + r0 + threadIdx.x] = tile[threadIdx.x][threadIdx.y + 8*s];
    }
}

// ---------------- transpose points1 -> split bf16 into g_Xhi/lo [col][256+r] ----
__global__ void transpose_split_kernel(const float* __restrict__ in)
{
    __shared__ float tile[32][33];
    int b  = blockIdx.z;
    int c0 = blockIdx.x * 32;   // point
    int r0 = blockIdx.y * 32;   // channel
    const float* ip = in + (size_t)b * C1 * Nq;
#pragma unroll
    for (int s = 0; s < 4; s++) {
        int r = r0 + threadIdx.y + 8*s;
        tile[threadIdx.y + 8*s][threadIdx.x] = ip[(size_t)r * Nq + c0 + threadIdx.x];
    }
    __syncthreads();
#pragma unroll
    for (int s = 0; s < 4; s++) {
        int c = c0 + threadIdx.y + 8*s;
        float v = tile[threadIdx.x][threadIdx.y + 8*s];
        unsigned short h, l;
        split_bf(v, h, l);
        size_t idx = ((size_t)b * Nq + c) * CIN + C2 + r0 + threadIdx.x;
        union { __nv_bfloat16 b16; unsigned short u; } cvh, cvl;
        cvh.u = h; cvl.u = l;
        g_Xhi[idx] = cvh.b16;
        g_Xlo[idx] = cvl.b16;
    }
}

// ---------------- 3-NN + weights + interpolation ---------------------------------
// Block: 64 queries x 8 chunk-groups (512 thr). Each thread scans a 256-ref chunk
// with 4-wide ILP batching + pairwise guarded branchy inserts (identical sequential
// semantics). 24 candidates merged in chunk-then-rank order.
#define KQ   64
#define KCH  8
#define KCHLEN (Mp/KCH)   // 256

__global__ __launch_bounds__(512) void knn_interp_kernel(
    const float* __restrict__ xyz1, const float* __restrict__ xyz2,
    const float* __restrict__ norm1, const float* __restrict__ norm2)
{
    __shared__ float4 sp[Mp];             // 32 KB
    __shared__ float  cd[3*KCH][KQ];      // 6 KB
    __shared__ int    ci[3*KCH][KQ];      // 6 KB
    __shared__ float  sw[3][KQ];
    __shared__ int    si[3][KQ];

    int b = blockIdx.y;
    int t = threadIdx.x;
    int qi = t & (KQ-1), c = t >> 6;

    const float* x2 = xyz2 + (size_t)b * 3 * Mp;
    for (int m = t; m < Mp; m += 512) {
        float a = x2[m], e = x2[Mp + m], d = x2[2*Mp + m];
        float4 v; v.x = a; v.y = e; v.z = d; v.w = a*a + e*e + d*d;
        sp[m] = v;
    }
    __syncthreads();

    int n = blockIdx.x * KQ + qi;
    const float* x1 = xyz1 + (size_t)b * 3 * Nq;
    float qx = x1[n], qy = x1[Nq + n], qz = x1[2*Nq + n];
    float qq = qx*qx + qy*qy + qz*qz;

    float d2_0 = 1e30f, d2_1 = 1e30f, d2_2v = 1e30f;
    int   i0 = 0, i1 = 0, i2 = 0;
    int mbase = c * KCHLEN;
#pragma unroll 2
    for (int mm = 0; mm < KCHLEN; mm += 4) {
        int m = mbase + mm;
        float4 P0 = sp[m], P1 = sp[m+1], P2 = sp[m+2], P3 = sp[m+3];
        float dot0 = qx*P0.x + qy*P0.y + qz*P0.z;
        float dot1 = qx*P1.x + qy*P1.y + qz*P1.z;
        float dot2 = qx*P2.x + qy*P2.y + qz*P2.z;
        float dot3 = qx*P3.x + qy*P3.y + qz*P3.z;
        float da = qq + P0.w - 2.0f*dot0;   // identical arithmetic to prior rounds
        float db = qq + P1.w - 2.0f*dot1;
        float dc = qq + P2.w - 2.0f*dot2;
        float dd = qq + P3.w - 2.0f*dot3;
        // guard == sequential semantics: if pair-min doesn't beat 3rd-best,
        // neither element would have updated anything
        if (fminf(da, db) < d2_2v) {
            top3_seq(da, m,   d2_0, d2_1, d2_2v, i0, i1, i2);
            top3_seq(db, m+1, d2_0, d2_1, d2_2v, i0, i1, i2);
        }
        if (fminf(dc, dd) < d2_2v) {
            top3_seq(dc, m+2, d2_0, d2_1, d2_2v, i0, i1, i2);
            top3_seq(dd, m+3, d2_0, d2_1, d2_2v, i0, i1, i2);
        }
    }
    cd[c*3+0][qi] = d2_0; ci[c*3+0][qi] = i0;
    cd[c*3+1][qi] = d2_1; ci[c*3+1][qi] = i1;
    cd[c*3+2][qi] = d2_2v; ci[c*3+2][qi] = i2;
    __syncthreads();

    if (c == 0) {
        float b0 = 1e30f, b1 = 1e30f, b2 = 1e30f;
        int   j0 = 0, j1 = 0, j2 = 0;
#pragma unroll
        for (int r = 0; r < 3*KCH; r++) {
            top3_seq(cd[r][qi], ci[r][qi], b0, b1, b2, j0, j1, j2);
        }
        float dist0 = sqrtf(fmaxf(b0, 1e-20f));
        float dist1 = sqrtf(fmaxf(b1, 1e-20f));
        float dist2 = sqrtf(fmaxf(b2, 1e-20f));

        const float* n1 = norm1 + (size_t)b * 3 * Nq;
        const float* n2 = norm2 + (size_t)b * 3 * Mp;
        float ax = n1[n], ay = n1[Nq+n], az = n1[2*Nq+n];
        float dx, dy, dz;
        dx = ax - n2[j0]; dy = ay - n2[Mp+j0]; dz = az - n2[2*Mp+j0];
        float nd0 = sqrtf(dx*dx + dy*dy + dz*dz);
        dx = ax - n2[j1]; dy = ay - n2[Mp+j1]; dz = az - n2[2*Mp+j1];
        float nd1 = sqrtf(dx*dx + dy*dy + dz*dz);
        dx = ax - n2[j2]; dy = ay - n2[Mp+j2]; dz = az - n2[2*Mp+j2];
        float nd2 = sqrtf(dx*dx + dy*dy + dz*dz);

        float r0 = 1.0f / fmaxf(dist0, 1e-10f);
        float r1 = 1.0f / fmaxf(dist1, 1e-10f);
        float r2 = 1.0f / fmaxf(dist2, 1e-10f);
        float rs = r0 + r1 + r2;
        float s0 = 1.0f / fmaxf(nd0, 1e-10f);
        float s1 = 1.0f / fmaxf(nd1, 1e-10f);
        float s2 = 1.0f / fmaxf(nd2, 1e-10f);
        float ssum = s0 + s1 + s2;
        sw[0][qi] = (r0 / rs) * (s0 / ssum);
        sw[1][qi] = (r1 / rs) * (s1 / ssum);
        sw[2][qi] = (r2 / rs) * (s2 / ssum);
        si[0][qi] = j0; si[1][qi] = j1; si[2][qi] = j2;
    }
    __syncthreads();

    // gather: 8 threads per query, 32 channels each
    float w0 = sw[0][qi], w1 = sw[1][qi], w2 = sw[2][qi];
    int   j0 = si[0][qi], j1 = si[1][qi], j2 = si[2][qi];
    size_t col = (size_t)b * Nq + n;
    int ch0 = c * 32;
    const float4* p0 = (const float4*)(g_p2T + ((size_t)b*Mp + j0) * C2 + ch0);
    const float4* p1 = (const float4*)(g_p2T + ((size_t)b*Mp + j1) * C2 + ch0);
    const float4* p2 = (const float4*)(g_p2T + ((size_t)b*Mp + j2) * C2 + ch0);
    uint2* xh = (uint2*)(g_Xhi + col * CIN + ch0);
    uint2* xl = (uint2*)(g_Xlo + col * CIN + ch0);
#pragma unroll
    for (int cc = 0; cc < 8; cc++) {
        float4 a = p0[cc], bq = p1[cc], cq = p2[cc];
        float r[4];
        r[0] = w0*a.x + w1*bq.x + w2*cq.x;
        r[1] = w0*a.y + w1*bq.y + w2*cq.y;
        r[2] = w0*a.z + w1*bq.z + w2*cq.z;
        r[3] = w0*a.w + w1*bq.w + w2*cq.w;
        unsigned short h[4], l[4];
#pragma unroll
        for (int j = 0; j < 4; j++) split_bf(r[j], h[j], l[j]);
        xh[cc] = make_uint2((uint32_t)h[0] | ((uint32_t)h[1]<<16),
                            (uint32_t)h[2] | ((uint32_t)h[3]<<16));
        xl[cc] = make_uint2((uint32_t)l[0] | ((uint32_t)l[1]<<16),
                            (uint32_t)l[2] | ((uint32_t)l[3]<<16));
    }
}

// ---------------- GEMM0 (mma.sync bf16x3): D[ch 128][pt 128] --------------------
#define SMA_H 0
#define SMA_L 16384
#define SMB_H 32768
#define SMB_L 49152
#define G0_SMEM (128*132*4)     // 67584

__global__ __launch_bounds__(256, 1) void gemm0_mma_kernel(const float* __restrict__ bias)
{
    extern __shared__ char sm[];
    uint32_t smb = smem_u32(sm);
    int t = threadIdx.x, lid = t & 31, wid = t >> 5;
    int wm = wid >> 2, wn = wid & 3;          // warps 2(m) x 4(n)
    int c0 = blockIdx.x * 128;                // point tile
    int m0 = blockIdx.y * 128;                // channel tile
    int sub = lid >> 3, rr = lid & 7;

    float acc[4][4][4];
#pragma unroll
    for (int i = 0; i < 4; i++)
#pragma unroll
        for (int j = 0; j < 4; j++)
#pragma unroll
            for (int q = 0; q < 4; q++) acc[i][j][q] = 0.f;

    for (int ck = 0; ck < 6; ck++) {
        int kk = ck * 64;
        __syncthreads();
        for (int i = t; i < 128*8; i += 256) {
            int r = i >> 3, j = i & 7;
            uint32_t so = (uint32_t)(r*128 + ((j ^ (r & 7)) << 4));
            *(uint4*)(sm + SMA_H + so) = *(const uint4*)(g_W0h + (size_t)(m0 + r)*CIN + kk + j*8);
            *(uint4*)(sm + SMA_L + so) = *(const uint4*)(g_W0l + (size_t)(m0 + r)*CIN + kk + j*8);
            *(uint4*)(sm + SMB_H + so) = *(const uint4*)(g_Xhi + (size_t)(c0 + r)*CIN + kk + j*8);
            *(uint4*)(sm + SMB_L + so) = *(const uint4*)(g_Xlo + (size_t)(c0 + r)*CIN + kk + j*8);
        }
        __syncthreads();
#pragma unroll
        for (int kb = 0; kb < 4; kb++) {
            int chnk = kb*2 + (sub >> 1);
            uint32_t Ah[4][4], Al[4][4], Bh[4][2], Bl[4][2];
#pragma unroll
            for (int i = 0; i < 4; i++) {
                int row = wm*64 + i*16 + ((sub & 1) << 3) + rr;
                uint32_t so = (uint32_t)(row*128 + ((chnk ^ rr) << 4));
                LDSM4(Ah[i], smb + SMA_H + so);
                LDSM4(Al[i], smb + SMA_L + so);
            }
#pragma unroll
            for (int jj = 0; jj < 2; jj++) {
                int row = wn*32 + jj*16 + ((sub & 1) << 3) + rr;
                uint32_t so = (uint32_t)(row*128 + ((chnk ^ rr) << 4));
                uint32_t rg[4];
                LDSM4(rg, smb + SMB_H + so);
                Bh[jj*2][0] = rg[0]; Bh[jj*2+1][0] = rg[1];
                Bh[jj*2][1] = rg[2]; Bh[jj*2+1][1] = rg[3];
                LDSM4(rg, smb + SMB_L + so);
                Bl[jj*2][0] = rg[0]; Bl[jj*2+1][0] = rg[1];
                Bl[jj*2][1] = rg[2]; Bl[jj*2+1][1] = rg[3];
            }
#pragma unroll
            for (int i = 0; i < 4; i++)
#pragma unroll
                for (int jt = 0; jt < 4; jt++) {
                    mma_bf16(acc[i][jt], Ah[i], Bh[jt]);
                    mma_bf16(acc[i][jt], Ah[i], Bl[jt]);
                    mma_bf16(acc[i][jt], Al[i], Bh[jt]);
                }
        }
    }

    // epilogue: transpose through smem -> g_Y0T [pt][ch], bn0 partials
    __syncthreads();
    float* s32 = (float*)sm;
#pragma unroll
    for (int i = 0; i < 4; i++) {
        int chr = wm*64 + i*16 + (lid >> 2);
#pragma unroll
        for (int jt = 0; jt < 4; jt++) {
            int pt = wn*32 + jt*8 + (lid & 3)*2;
            s32[(size_t)pt*132 + chr]       = acc[i][jt][0];
            s32[(size_t)(pt+1)*132 + chr]   = acc[i][jt][1];
            s32[(size_t)pt*132 + chr + 8]   = acc[i][jt][2];
            s32[(size_t)(pt+1)*132 + chr+8] = acc[i][jt][3];
        }
    }
    __syncthreads();
    int chn = t & 127, half = t >> 7;
    float bi = bias[m0 + chn];
    float s = 0.f, q = 0.f;
    for (int p = half*64; p < half*64 + 64; p++) {
        float v = s32[(size_t)p*132 + chn] + bi;
        s += v; q += v*v;
        g_Y0T[(size_t)(c0 + p)*CO0 + m0 + chn] = v;
    }
    g_p0s[(size_t)(blockIdx.x*2 + half)*CO0 + m0 + chn] = s;
    g_p0q[(size_t)(blockIdx.x*2 + half)*CO0 + m0 + chn] = q;
}

// ---------------- bn0 partial reduce -> scale0/shift0 ---------------------------
__global__ __launch_bounds__(256) void reduce0_kernel(const float* __restrict__ g,
                                                      const float* __restrict__ be)
{
    int chn = blockIdx.x, t = threadIdx.x;
    double s = (double)g_p0s[(size_t)t*CO0 + chn] + (double)g_p0s[(size_t)(t+256)*CO0 + chn];
    double q = (double)g_p0q[(size_t)t*CO0 + chn] + (double)g_p0q[(size_t)(t+256)*CO0 + chn];
    __shared__ double ss[256], qq[256];
    ss[t] = s; qq[t] = q;
    __syncthreads();
    for (int st = 128; st > 0; st >>= 1) {
        if (t < st) { ss[t] += ss[t+st]; qq[t] += qq[t+st]; }
        __syncthreads();
    }
    if (t == 0) {
        double inv = 1.0 / (double)NC;
        double mean = ss[0] * inv;
        double var  = qq[0] * inv - mean*mean;
        double sc   = (double)g[chn] / sqrt(var + 1e-5);
        g_scale0[chn] = (float)sc;
        g_shift0[chn] = (float)((double)be[chn] - mean * sc);
    }
}

// ---------------- GEMM1 (mma.sync bf16x3): D[ch 128][pt 128] -> d_out -----------
#define G1_SMEM (65536 + 2048)

__global__ __launch_bounds__(256, 1) void gemm1_mma_kernel(const float* __restrict__ bias,
                                                           float* __restrict__ out)
{
    extern __shared__ char sm[];
    uint32_t smb = smem_u32(sm);
    float* s_sc = (float*)(sm + 65536);
    float* s_sh = (float*)(sm + 65536 + 1024);
    int t = threadIdx.x, lid = t & 31, wid = t >> 5;
    int wm = wid >> 2, wn = wid & 3;
    int p0 = blockIdx.x * 128;
    int sub = lid >> 3, rr = lid & 7;

    s_sc[t] = g_scale0[t];
    s_sh[t] = g_shift0[t];

    float acc[4][4][4];
#pragma unroll
    for (int i = 0; i < 4; i++)
#pragma unroll
        for (int j = 0; j < 4; j++)
#pragma unroll
            for (int q = 0; q < 4; q++) acc[i][j][q] = 0.f;

    for (int ck = 0; ck < 4; ck++) {
        int kk = ck * 64;
        __syncthreads();
        for (int i = t; i < 128*8; i += 256) {
            int r = i >> 3, j = i & 7;
            uint32_t so = (uint32_t)(r*128 + ((j ^ (r & 7)) << 4));
            *(uint4*)(sm + SMA_H + so) = *(const uint4*)(g_W1h + (size_t)r*CO0 + kk + j*8);
            *(uint4*)(sm + SMA_L + so) = *(const uint4*)(g_W1l + (size_t)r*CO0 + kk + j*8);
            const float* yp = g_Y0T + (size_t)(p0 + r)*CO0 + kk + j*8;
            float v[8];
#pragma unroll
            for (int q = 0; q < 8; q++) {
                int k = kk + j*8 + q;
                v[q] = fmaxf(0.f, fmaf(yp[q], s_sc[k], s_sh[k]));
            }
            uint4 h4, l4;
            split8(v, h4, l4);
            *(uint4*)(sm + SMB_H + so) = h4;
            *(uint4*)(sm + SMB_L + so) = l4;
        }
        __syncthreads();
#pragma unroll
        for (int kb = 0; kb < 4; kb++) {
            int chnk = kb*2 + (sub >> 1);
            uint32_t Ah[4][4], Al[4][4], Bh[4][2], Bl[4][2];
#pragma unroll
            for (int i = 0; i < 4; i++) {
                int row = wm*64 + i*16 + ((sub & 1) << 3) + rr;
                uint32_t so = (uint32_t)(row*128 + ((chnk ^ rr) << 4));
                LDSM4(Ah[i], smb + SMA_H + so);
                LDSM4(Al[i], smb + SMA_L + so);
            }
#pragma unroll
            for (int jj = 0; jj < 2; jj++) {
                int row = wn*32 + jj*16 + ((sub & 1) << 3) + rr;
                uint32_t so = (uint32_t)(row*128 + ((chnk ^ rr) << 4));
                uint32_t rg[4];
                LDSM4(rg, smb + SMB_H + so);
                Bh[jj*2][0] = rg[0]; Bh[jj*2+1][0] = rg[1];
                Bh[jj*2][1] = rg[2]; Bh[jj*2+1][1] = rg[3];
                LDSM4(rg, smb + SMB_L + so);
                Bl[jj*2][0] = rg[0]; Bl[jj*2+1][0] = rg[1];
                Bl[jj*2][1] = rg[2]; Bl[jj*2+1][1] = rg[3];
            }
#pragma unroll
            for (int i = 0; i < 4; i++)
#pragma unroll
                for (int jt = 0; jt < 4; jt++) {
                    mma_bf16(acc[i][jt], Ah[i], Bh[jt]);
                    mma_bf16(acc[i][jt], Ah[i], Bl[jt]);
                    mma_bf16(acc[i][jt], Al[i], Bh[jt]);
                }
        }
    }

#pragma unroll
    for (int i = 0; i < 4; i++) {
        int ch = wm*64 + i*16 + (lid >> 2);
        float b0v = bias[ch], b8v = bias[ch + 8];
#pragma unroll
        for (int jt = 0; jt < 4; jt++) {
            int ptl = wn*32 + jt*8 + (lid & 3)*2;
            int gp = p0 + ptl;
            int b = gp >> 13, n = gp & (Nq - 1);
            float2 v0 = make_float2(acc[i][jt][0] + b0v, acc[i][jt][1] + b0v);
            float2 v1 = make_float2(acc[i][jt][2] + b8v, acc[i][jt][3] + b8v);
            *(float2*)(out + ((size_t)b*CO1 + ch)*Nq + n)     = v0;
            *(float2*)(out + ((size_t)b*CO1 + ch + 8)*Nq + n) = v1;
        }
    }
}

// ---------------- per-channel BN stats (bn1 over d_out) -------------------------
__global__ __launch_bounds__(256) void stats_kernel(const float* __restrict__ Y,
    const float* __restrict__ g, const float* __restrict__ be,
    float* __restrict__ scale, float* __restrict__ shift,
    long long chan_stride, int nchunks, long long chunk_stride, int chunk_len, float inv_count)
{
    int o = blockIdx.x;
    int tid = threadIdx.x;
    float s = 0.f, q = 0.f;
    for (int cb = 0; cb < nchunks; cb++) {
        const float4* p = (const float4*)(Y + (size_t)o * chan_stride + (size_t)cb * chunk_stride);
        int len4 = chunk_len >> 2;
        for (int i = tid; i < len4; i += 256) {
            float4 v = p[i];
            s += (v.x + v.y) + (v.z + v.w);
            q += (v.x*v.x + v.y*v.y) + (v.z*v.z + v.w*v.w);
        }
    }
    __shared__ double ss[256], sq[256];
    ss[tid] = (double)s; sq[tid] = (double)q;
    __syncthreads();
    for (int st = 128; st > 0; st >>= 1) {
        if (tid < st) { ss[tid] += ss[tid+st]; sq[tid] += sq[tid+st]; }
        __syncthreads();
    }
    if (tid == 0) {
        double mean = ss[0] * (double)inv_count;
        double var  = sq[0] * (double)inv_count - mean*mean;
        double sc   = (double)g[o] / sqrt(var + 1e-5);
        scale[o] = (float)sc;
        shift[o] = (float)((double)be[o] - mean * sc);
    }
}

// ---------------- final BN + ReLU, in place on d_out ----------------------------
__global__ __launch_bounds__(256) void bnrelu_kernel(float* __restrict__ out)
{
    int i = blockIdx.x * 256 + threadIdx.x;
    int o = (i >> 11) & 127;
    float sc = g_scale1[o], sh = g_shift1[o];
    float4* p = (float4*)out;
    float4 v = p[i];
    v.x = fmaxf(0.f, fmaf(v.x, sc, sh));
    v.y = fmaxf(0.f, fmaf(v.y, sc, sh));
    v.z = fmaxf(0.f, fmaf(v.z, sc, sh));
    v.w = fmaxf(0.f, fmaf(v.w, sc, sh));
    p[i] = v;
}

// ---------------- launch ---------------------------------------------------------
extern "C" void kernel_launch(void* const* d_in, const int* in_sizes, int n_in,
                              void* d_out, int out_size)
{
    const float* xyz1    = (const float*)d_in[0];
    const float* xyz2    = (const float*)d_in[1];
    const float* norm1   = (const float*)d_in[2];
    const float* norm2   = (const float*)d_in[3];
    const float* points1 = (const float*)d_in[4];
    const float* points2 = (const float*)d_in[5];
    const float* W0      = (const float*)d_in[6];
    const float* b0      = (const float*)d_in[7];
    const float* g0      = (const float*)d_in[8];
    const float* be0     = (const float*)d_in[9];
    const float* W1      = (const float*)d_in[10];
    const float* b1      = (const float*)d_in[11];
    const float* g1      = (const float*)d_in[12];
    const float* be1     = (const float*)d_in[13];
    float* out = (float*)d_out;

    cudaFuncSetAttribute(gemm0_mma_kernel, cudaFuncAttributeMaxDynamicSharedMemorySize, G0_SMEM);
    cudaFuncSetAttribute(gemm1_mma_kernel, cudaFuncAttributeMaxDynamicSharedMemorySize, G1_SMEM);

    float *p2T_ptr, *sc1, *sh1;
    cudaGetSymbolAddress((void**)&p2T_ptr, g_p2T);
    cudaGetSymbolAddress((void**)&sc1, g_scale1);
    cudaGetSymbolAddress((void**)&sh1, g_shift1);

    // weight presplit (bf16 hi/lo)
    splitw_kernel<<<(CO0*CIN + CO1*CO0 + 255)/256, 256>>>(W0, W1);
    // points2 (B,256,2048) -> g_p2T (B,2048,256) fp32
    transpose_kernel<<<dim3(Mp/32, C2/32, Bsz), dim3(32,8)>>>(points2, p2T_ptr, C2, Mp, C2);
    // points1 -> split bf16 into g_Xhi/lo [col][256..383]
    transpose_split_kernel<<<dim3(Nq/32, C1/32, Bsz), dim3(32,8)>>>(points1);
    // 3-NN + interpolation -> g_Xhi/lo [col][0..255]
    knn_interp_kernel<<<dim3(Nq/KQ, Bsz), 512>>>(xyz1, xyz2, norm1, norm2);
    // conv0 (HMMA bf16x3) -> g_Y0T [pt][ch] + bn0 partials
    gemm0_mma_kernel<<<dim3(NC/128, CO0/128), 256, G0_SMEM>>>(b0);
    // bn0 affine
    reduce0_kernel<<<CO0, 256>>>(g0, be0);
    // conv1 (HMMA bf16x3, bn0+relu fused in staging) -> d_out raw
    gemm1_mma_kernel<<<dim3(NC/128), 256, G1_SMEM>>>(b1, out);
    // bn1 stats over d_out raw
    stats_kernel<<<CO1, 256>>>(out, g1, be1, sc1, sh1,
                               (long long)Nq, Bsz, (long long)(CO1*Nq), Nq, 1.0f/(float)NC);
    // final bn1 + relu in place
    bnrelu_kernel<<<(Bsz*CO1*Nq/4)/256, 256>>>(out);
}

// round 17
// speedup vs baseline: 1.0824x; 1.0272x over previous
#include <cuda_runtime.h>
#include <cuda_bf16.h>
#include <math.h>
#include <stdint.h>

#define Bsz 4
#define Nq  8192
#define Mp  2048
#define C1  128
#define C2  256
#define CIN 384
#define CO0 256
#define CO1 128
#define NC  (Bsz*Nq)   // 32768

// ---------------- scratch (static device globals; no allocation) ----------------
__device__ float g_p2T[Bsz*Mp*C2];                       // points2^T (B,M,C2) fp32
__device__ __nv_bfloat16 g_Xhi[(size_t)NC*CIN];          // X hi split [col][k]
__device__ __nv_bfloat16 g_Xlo[(size_t)NC*CIN];          // X lo split [col][k]
__device__ __nv_bfloat16 g_W0h[CO0*CIN], g_W0l[CO0*CIN];
__device__ __nv_bfloat16 g_W1h[CO1*CO0], g_W1l[CO1*CO0];
__device__ float g_Y0T[(size_t)NC*CO0];                  // conv0 out [pt][ch] fp32
__device__ float g_p0s[512*CO0], g_p0q[512*CO0];         // bn0 partials
__device__ float g_scale0[CO0], g_shift0[CO0];
__device__ float g_scale1[CO1], g_shift1[CO1];

// ---------------- helpers --------------------------------------------------------
__device__ __forceinline__ uint32_t smem_u32(const void* p) {
    uint32_t a;
    asm("{ .reg .u64 t; cvta.to.shared.u64 t, %1; cvt.u32.u64 %0, t; }" : "=r"(a) : "l"(p));
    return a;
}

#define LDSM4(r, addr) \
    asm volatile("ldmatrix.sync.aligned.m8n8.x4.shared.b16 {%0,%1,%2,%3}, [%4];" \
        : "=r"((r)[0]),"=r"((r)[1]),"=r"((r)[2]),"=r"((r)[3]) : "r"(addr))

__device__ __forceinline__ void mma_bf16(float* d, const uint32_t* a, const uint32_t* b) {
    asm volatile("mma.sync.aligned.m16n8k16.row.col.f32.bf16.bf16.f32 "
        "{%0,%1,%2,%3}, {%4,%5,%6,%7}, {%8,%9}, {%0,%1,%2,%3};"
        : "+f"(d[0]), "+f"(d[1]), "+f"(d[2]), "+f"(d[3])
        : "r"(a[0]), "r"(a[1]), "r"(a[2]), "r"(a[3]), "r"(b[0]), "r"(b[1]));
}

// packed f32x2 ops (PTX-only; ptxas never auto-fuses)
#define MUL_F32X2(d, a, b)     asm("mul.rn.f32x2 %0, %1, %2;" : "=l"(d) : "l"(a), "l"(b))
#define FMA_F32X2(d, a, b, c)  asm("fma.rn.f32x2 %0, %1, %2, %3;" : "=l"(d) : "l"(a), "l"(b), "l"(c))
#define PACK_F32X2(d, lo, hi)  asm("mov.b64 %0, {%1, %2};" : "=l"(d) : "f"(lo), "f"(hi))
#define UNPACK_F32X2(lo, hi, s) asm("mov.b64 {%0, %1}, %2;" : "=f"(lo), "=f"(hi) : "l"(s))

__device__ __forceinline__ void split_bf(float v, unsigned short& h, unsigned short& l) {
    __nv_bfloat16 hb = __float2bfloat16(v);
    float hf = __bfloat162float(hb);
    __nv_bfloat16 lb = __float2bfloat16(v - hf);
    union { __nv_bfloat16 b; unsigned short u; } ch, cl;
    ch.b = hb; cl.b = lb;
    h = ch.u; l = cl.u;
}

__device__ __forceinline__ void split8(const float* v, uint4& h4, uint4& l4) {
    unsigned short h[8], l[8];
#pragma unroll
    for (int i = 0; i < 8; i++) split_bf(v[i], h[i], l[i]);
    h4 = make_uint4((uint32_t)h[0]|((uint32_t)h[1]<<16), (uint32_t)h[2]|((uint32_t)h[3]<<16),
                    (uint32_t)h[4]|((uint32_t)h[5]<<16), (uint32_t)h[6]|((uint32_t)h[7]<<16));
    l4 = make_uint4((uint32_t)l[0]|((uint32_t)l[1]<<16), (uint32_t)l[2]|((uint32_t)l[3]<<16),
                    (uint32_t)l[4]|((uint32_t)l[5]<<16), (uint32_t)l[6]|((uint32_t)l[7]<<16));
}

// sequential top-3 insert (strict <, ties keep earlier candidate)
__device__ __forceinline__ void top3_seq(float d2, int m,
    float& d0, float& d1, float& d2_, int& i0, int& i1, int& i2)
{
    if (d2 < d2_) {
        if (d2 < d1) {
            d2_ = d1; i2 = i1;
            if (d2 < d0) { d1 = d0; i1 = i0; d0 = d2; i0 = m; }
            else         { d1 = d2; i1 = m; }
        } else { d2_ = d2; i2 = m; }
    }
}

// ---------------- weight presplit ------------------------------------------------
__global__ void splitw_kernel(const float* __restrict__ W0, const float* __restrict__ W1)
{
    int i = blockIdx.x * 256 + threadIdx.x;
    if (i < CO0*CIN) {
        unsigned short h, l; split_bf(W0[i], h, l);
        union { __nv_bfloat16 b; unsigned short u; } ch, cl; ch.u = h; cl.u = l;
        g_W0h[i] = ch.b; g_W0l[i] = cl.b;
    }
    int j = i - CO0*CIN;
    if (j >= 0 && j < CO1*CO0) {
        unsigned short h, l; split_bf(W1[j], h, l);
        union { __nv_bfloat16 b; unsigned short u; } ch, cl; ch.u = h; cl.u = l;
        g_W1h[j] = ch.b; g_W1l[j] = cl.b;
    }
}

// ---------------- transpose (fp32): in (B,R,C) -> out[(b*C+c)*ostride + r] -------
__global__ void transpose_kernel(const float* __restrict__ in, float* __restrict__ out,
                                 int R, int C, int ostride)
{
    __shared__ float tile[32][33];
    int b  = blockIdx.z;
    int c0 = blockIdx.x * 32;
    int r0 = blockIdx.y * 32;
    const float* ip = in + (size_t)b * R * C;
#pragma unroll
    for (int s = 0; s < 4; s++) {
        int r = r0 + threadIdx.y + 8*s;
        tile[threadIdx.y + 8*s][threadIdx.x] = ip[(size_t)r * C + c0 + threadIdx.x];
    }
    __syncthreads();
#pragma unroll
    for (int s = 0; s < 4; s++) {
        int c = c0 + threadIdx.y + 8*s;
        out[((size_t)b * C + c) * ostride + r0 + threadIdx.x] = tile[threadIdx.x][threadIdx.y + 8*s];
    }
}

// ---------------- transpose points1 -> split bf16 into g_Xhi/lo [col][256+r] ----
__global__ void transpose_split_kernel(const float* __restrict__ in)
{
    __shared__ float tile[32][33];
    int b  = blockIdx.z;
    int c0 = blockIdx.x * 32;   // point
    int r0 = blockIdx.y * 32;   // channel
    const float* ip = in + (size_t)b * C1 * Nq;
#pragma unroll
    for (int s = 0; s < 4; s++) {
        int r = r0 + threadIdx.y + 8*s;
        tile[threadIdx.y + 8*s][threadIdx.x] = ip[(size_t)r * Nq + c0 + threadIdx.x];
    }
    __syncthreads();
#pragma unroll
    for (int s = 0; s < 4; s++) {
        int c = c0 + threadIdx.y + 8*s;
        float v = tile[threadIdx.x][threadIdx.y + 8*s];
        unsigned short h, l;
        split_bf(v, h, l);
        size_t idx = ((size_t)b * Nq + c) * CIN + C2 + r0 + threadIdx.x;
        union { __nv_bfloat16 b16; unsigned short u; } cvh, cvl;
        cvh.u = h; cvl.u = l;
        g_Xhi[idx] = cvh.b16;
        g_Xlo[idx] = cvl.b16;
    }
}

// ---------------- 3-NN + weights + interpolation (f32x2 packed scan) ------------
// Block: 64 queries x 8 chunk-groups (512 thr). SoA smem; scan key = pp - 2*dot
// (qq is a per-query constant shift -> ordering identical; added back for dist).
#define KQ   64
#define KCH  8
#define KCHLEN (Mp/KCH)   // 256

__global__ __launch_bounds__(512) void knn_interp_kernel(
    const float* __restrict__ xyz1, const float* __restrict__ xyz2,
    const float* __restrict__ norm1, const float* __restrict__ norm2)
{
    __shared__ __align__(16) float spx[Mp], spy[Mp], spz[Mp], spw[Mp];  // 32 KB
    __shared__ float  cd[3*KCH][KQ];      // 6 KB  (keys)
    __shared__ int    ci[3*KCH][KQ];      // 6 KB
    __shared__ float  sw[3][KQ];
    __shared__ int    si[3][KQ];

    int b = blockIdx.y;
    int t = threadIdx.x;
    int qi = t & (KQ-1), c = t >> 6;

    const float* x2 = xyz2 + (size_t)b * 3 * Mp;
    for (int m = t; m < Mp; m += 512) {
        float a = x2[m], e = x2[Mp + m], d = x2[2*Mp + m];
        spx[m] = a; spy[m] = e; spz[m] = d;
        spw[m] = a*a + e*e + d*d;
    }
    __syncthreads();

    int n = blockIdx.x * KQ + qi;
    const float* x1 = xyz1 + (size_t)b * 3 * Nq;
    float qx = x1[n], qy = x1[Nq + n], qz = x1[2*Nq + n];
    float qq = qx*qx + qy*qy + qz*qz;

    uint64_t qx2, qy2, qz2, c2m;
    PACK_F32X2(qx2, qx, qx);
    PACK_F32X2(qy2, qy, qy);
    PACK_F32X2(qz2, qz, qz);
    PACK_F32X2(c2m, -2.0f, -2.0f);

    float k0 = 1e30f, k1 = 1e30f, k2v = 1e30f;
    int   i0 = 0, i1 = 0, i2 = 0;
    int mbase = c * KCHLEN;
#pragma unroll 2
    for (int mm = 0; mm < KCHLEN; mm += 4) {
        int m = mbase + mm;
        ulonglong2 Xp = *(const ulonglong2*)&spx[m];
        ulonglong2 Yp = *(const ulonglong2*)&spy[m];
        ulonglong2 Zp = *(const ulonglong2*)&spz[m];
        ulonglong2 Wp = *(const ulonglong2*)&spw[m];
        uint64_t dotA, dotB, kA, kB;
        MUL_F32X2(dotA, qx2, Xp.x);
        FMA_F32X2(dotA, qy2, Yp.x, dotA);
        FMA_F32X2(dotA, qz2, Zp.x, dotA);
        FMA_F32X2(kA, c2m, dotA, Wp.x);      // key = pp - 2*dot
        MUL_F32X2(dotB, qx2, Xp.y);
        FMA_F32X2(dotB, qy2, Yp.y, dotB);
        FMA_F32X2(dotB, qz2, Zp.y, dotB);
        FMA_F32X2(kB, c2m, dotB, Wp.y);
        float ka0, ka1, kb0, kb1;
        UNPACK_F32X2(ka0, ka1, kA);
        UNPACK_F32X2(kb0, kb1, kB);
        if (fminf(ka0, ka1) < k2v) {
            top3_seq(ka0, m,   k0, k1, k2v, i0, i1, i2);
            top3_seq(ka1, m+1, k0, k1, k2v, i0, i1, i2);
        }
        if (fminf(kb0, kb1) < k2v) {
            top3_seq(kb0, m+2, k0, k1, k2v, i0, i1, i2);
            top3_seq(kb1, m+3, k0, k1, k2v, i0, i1, i2);
        }
    }
    cd[c*3+0][qi] = k0;  ci[c*3+0][qi] = i0;
    cd[c*3+1][qi] = k1;  ci[c*3+1][qi] = i1;
    cd[c*3+2][qi] = k2v; ci[c*3+2][qi] = i2;
    __syncthreads();

    if (c == 0) {
        float b0 = 1e30f, b1 = 1e30f, b2 = 1e30f;
        int   j0 = 0, j1 = 0, j2 = 0;
#pragma unroll
        for (int r = 0; r < 3*KCH; r++) {
            top3_seq(cd[r][qi], ci[r][qi], b0, b1, b2, j0, j1, j2);
        }
        // d2 = key + qq
        float dist0 = sqrtf(fmaxf(b0 + qq, 1e-20f));
        float dist1 = sqrtf(fmaxf(b1 + qq, 1e-20f));
        float dist2 = sqrtf(fmaxf(b2 + qq, 1e-20f));

        const float* n1 = norm1 + (size_t)b * 3 * Nq;
        const float* n2 = norm2 + (size_t)b * 3 * Mp;
        float ax = n1[n], ay = n1[Nq+n], az = n1[2*Nq+n];
        float dx, dy, dz;
        dx = ax - n2[j0]; dy = ay - n2[Mp+j0]; dz = az - n2[2*Mp+j0];
        float nd0 = sqrtf(dx*dx + dy*dy + dz*dz);
        dx = ax - n2[j1]; dy = ay - n2[Mp+j1]; dz = az - n2[2*Mp+j1];
        float nd1 = sqrtf(dx*dx + dy*dy + dz*dz);
        dx = ax - n2[j2]; dy = ay - n2[Mp+j2]; dz = az - n2[2*Mp+j2];
        float nd2 = sqrtf(dx*dx + dy*dy + dz*dz);

        float r0 = 1.0f / fmaxf(dist0, 1e-10f);
        float r1 = 1.0f / fmaxf(dist1, 1e-10f);
        float r2 = 1.0f / fmaxf(dist2, 1e-10f);
        float rs = r0 + r1 + r2;
        float s0 = 1.0f / fmaxf(nd0, 1e-10f);
        float s1 = 1.0f / fmaxf(nd1, 1e-10f);
        float s2 = 1.0f / fmaxf(nd2, 1e-10f);
        float ssum = s0 + s1 + s2;
        sw[0][qi] = (r0 / rs) * (s0 / ssum);
        sw[1][qi] = (r1 / rs) * (s1 / ssum);
        sw[2][qi] = (r2 / rs) * (s2 / ssum);
        si[0][qi] = j0; si[1][qi] = j1; si[2][qi] = j2;
    }
    __syncthreads();

    // gather: 8 threads per query, 32 channels each
    float w0 = sw[0][qi], w1 = sw[1][qi], w2 = sw[2][qi];
    int   j0 = si[0][qi], j1 = si[1][qi], j2 = si[2][qi];
    size_t col = (size_t)b * Nq + n;
    int ch0 = c * 32;
    const float4* p0 = (const float4*)(g_p2T + ((size_t)b*Mp + j0) * C2 + ch0);
    const float4* p1 = (const float4*)(g_p2T + ((size_t)b*Mp + j1) * C2 + ch0);
    const float4* p2 = (const float4*)(g_p2T + ((size_t)b*Mp + j2) * C2 + ch0);
    uint2* xh = (uint2*)(g_Xhi + col * CIN + ch0);
    uint2* xl = (uint2*)(g_Xlo + col * CIN + ch0);
#pragma unroll
    for (int cc = 0; cc < 8; cc++) {
        float4 a = p0[cc], bq = p1[cc], cq = p2[cc];
        float r[4];
        r[0] = w0*a.x + w1*bq.x + w2*cq.x;
        r[1] = w0*a.y + w1*bq.y + w2*cq.y;
        r[2] = w0*a.z + w1*bq.z + w2*cq.z;
        r[3] = w0*a.w + w1*bq.w + w2*cq.w;
        unsigned short h[4], l[4];
#pragma unroll
        for (int j = 0; j < 4; j++) split_bf(r[j], h[j], l[j]);
        xh[cc] = make_uint2((uint32_t)h[0] | ((uint32_t)h[1]<<16),
                            (uint32_t)h[2] | ((uint32_t)h[3]<<16));
        xl[cc] = make_uint2((uint32_t)l[0] | ((uint32_t)l[1]<<16),
                            (uint32_t)l[2] | ((uint32_t)l[3]<<16));
    }
}

// ---------------- GEMM0 (mma.sync bf16x3): D[ch 128][pt 128] --------------------
#define SMA_H 0
#define SMA_L 16384
#define SMB_H 32768
#define SMB_L 49152
#define G0_SMEM (128*132*4)     // 67584

__global__ __launch_bounds__(256, 1) void gemm0_mma_kernel(const float* __restrict__ bias)
{
    extern __shared__ char sm[];
    uint32_t smb = smem_u32(sm);
    int t = threadIdx.x, lid = t & 31, wid = t >> 5;
    int wm = wid >> 2, wn = wid & 3;          // warps 2(m) x 4(n)
    int c0 = blockIdx.x * 128;                // point tile
    int m0 = blockIdx.y * 128;                // channel tile
    int sub = lid >> 3, rr = lid & 7;

    float acc[4][4][4];
#pragma unroll
    for (int i = 0; i < 4; i++)
#pragma unroll
        for (int j = 0; j < 4; j++)
#pragma unroll
            for (int q = 0; q < 4; q++) acc[i][j][q] = 0.f;

    for (int ck = 0; ck < 6; ck++) {
        int kk = ck * 64;
        __syncthreads();
        for (int i = t; i < 128*8; i += 256) {
            int r = i >> 3, j = i & 7;
            uint32_t so = (uint32_t)(r*128 + ((j ^ (r & 7)) << 4));
            *(uint4*)(sm + SMA_H + so) = *(const uint4*)(g_W0h + (size_t)(m0 + r)*CIN + kk + j*8);
            *(uint4*)(sm + SMA_L + so) = *(const uint4*)(g_W0l + (size_t)(m0 + r)*CIN + kk + j*8);
            *(uint4*)(sm + SMB_H + so) = *(const uint4*)(g_Xhi + (size_t)(c0 + r)*CIN + kk + j*8);
            *(uint4*)(sm + SMB_L + so) = *(const uint4*)(g_Xlo + (size_t)(c0 + r)*CIN + kk + j*8);
        }
        __syncthreads();
#pragma unroll
        for (int kb = 0; kb < 4; kb++) {
            int chnk = kb*2 + (sub >> 1);
            uint32_t Ah[4][4], Al[4][4], Bh[4][2], Bl[4][2];
#pragma unroll
            for (int i = 0; i < 4; i++) {
                int row = wm*64 + i*16 + ((sub & 1) << 3) + rr;
                uint32_t so = (uint32_t)(row*128 + ((chnk ^ rr) << 4));
                LDSM4(Ah[i], smb + SMA_H + so);
                LDSM4(Al[i], smb + SMA_L + so);
            }
#pragma unroll
            for (int jj = 0; jj < 2; jj++) {
                int row = wn*32 + jj*16 + ((sub & 1) << 3) + rr;
                uint32_t so = (uint32_t)(row*128 + ((chnk ^ rr) << 4));
                uint32_t rg[4];
                LDSM4(rg, smb + SMB_H + so);
                Bh[jj*2][0] = rg[0]; Bh[jj*2+1][0] = rg[1];
                Bh[jj*2][1] = rg[2]; Bh[jj*2+1][1] = rg[3];
                LDSM4(rg, smb + SMB_L + so);
                Bl[jj*2][0] = rg[0]; Bl[jj*2+1][0] = rg[1];
                Bl[jj*2][1] = rg[2]; Bl[jj*2+1][1] = rg[3];
            }
#pragma unroll
            for (int i = 0; i < 4; i++)
#pragma unroll
                for (int jt = 0; jt < 4; jt++) {
                    mma_bf16(acc[i][jt], Ah[i], Bh[jt]);
                    mma_bf16(acc[i][jt], Ah[i], Bl[jt]);
                    mma_bf16(acc[i][jt], Al[i], Bh[jt]);
                }
        }
    }

    // epilogue: transpose through smem -> g_Y0T [pt][ch], bn0 partials
    __syncthreads();
    float* s32 = (float*)sm;
#pragma unroll
    for (int i = 0; i < 4; i++) {
        int chr = wm*64 + i*16 + (lid >> 2);
#pragma unroll
        for (int jt = 0; jt < 4; jt++) {
            int pt = wn*32 + jt*8 + (lid & 3)*2;
            s32[(size_t)pt*132 + chr]       = acc[i][jt][0];
            s32[(size_t)(pt+1)*132 + chr]   = acc[i][jt][1];
            s32[(size_t)pt*132 + chr + 8]   = acc[i][jt][2];
            s32[(size_t)(pt+1)*132 + chr+8] = acc[i][jt][3];
        }
    }
    __syncthreads();
    int chn = t & 127, half = t >> 7;
    float bi = bias[m0 + chn];
    float s = 0.f, q = 0.f;
    for (int p = half*64; p < half*64 + 64; p++) {
        float v = s32[(size_t)p*132 + chn] + bi;
        s += v; q += v*v;
        g_Y0T[(size_t)(c0 + p)*CO0 + m0 + chn] = v;
    }
    g_p0s[(size_t)(blockIdx.x*2 + half)*CO0 + m0 + chn] = s;
    g_p0q[(size_t)(blockIdx.x*2 + half)*CO0 + m0 + chn] = q;
}

// ---------------- bn0 partial reduce -> scale0/shift0 ---------------------------
__global__ __launch_bounds__(256) void reduce0_kernel(const float* __restrict__ g,
                                                      const float* __restrict__ be)
{
    int chn = blockIdx.x, t = threadIdx.x;
    double s = (double)g_p0s[(size_t)t*CO0 + chn] + (double)g_p0s[(size_t)(t+256)*CO0 + chn];
    double q = (double)g_p0q[(size_t)t*CO0 + chn] + (double)g_p0q[(size_t)(t+256)*CO0 + chn];
    __shared__ double ss[256], qq[256];
    ss[t] = s; qq[t] = q;
    __syncthreads();
    for (int st = 128; st > 0; st >>= 1) {
        if (t < st) { ss[t] += ss[t+st]; qq[t] += qq[t+st]; }
        __syncthreads();
    }
    if (t == 0) {
        double inv = 1.0 / (double)NC;
        double mean = ss[0] * inv;
        double var  = qq[0] * inv - mean*mean;
        double sc   = (double)g[chn] / sqrt(var + 1e-5);
        g_scale0[chn] = (float)sc;
        g_shift0[chn] = (float)((double)be[chn] - mean * sc);
    }
}

// ---------------- GEMM1 (mma.sync bf16x3): D[ch 128][pt 128] -> d_out -----------
#define G1_SMEM (65536 + 2048)

__global__ __launch_bounds__(256, 1) void gemm1_mma_kernel(const float* __restrict__ bias,
                                                           float* __restrict__ out)
{
    extern __shared__ char sm[];
    uint32_t smb = smem_u32(sm);
    float* s_sc = (float*)(sm + 65536);
    float* s_sh = (float*)(sm + 65536 + 1024);
    int t = threadIdx.x, lid = t & 31, wid = t >> 5;
    int wm = wid >> 2, wn = wid & 3;
    int p0 = blockIdx.x * 128;
    int sub = lid >> 3, rr = lid & 7;

    s_sc[t] = g_scale0[t];
    s_sh[t] = g_shift0[t];

    float acc[4][4][4];
#pragma unroll
    for (int i = 0; i < 4; i++)
#pragma unroll
        for (int j = 0; j < 4; j++)
#pragma unroll
            for (int q = 0; q < 4; q++) acc[i][j][q] = 0.f;

    for (int ck = 0; ck < 4; ck++) {
        int kk = ck * 64;
        __syncthreads();
        for (int i = t; i < 128*8; i += 256) {
            int r = i >> 3, j = i & 7;
            uint32_t so = (uint32_t)(r*128 + ((j ^ (r & 7)) << 4));
            *(uint4*)(sm + SMA_H + so) = *(const uint4*)(g_W1h + (size_t)r*CO0 + kk + j*8);
            *(uint4*)(sm + SMA_L + so) = *(const uint4*)(g_W1l + (size_t)r*CO0 + kk + j*8);
            const float* yp = g_Y0T + (size_t)(p0 + r)*CO0 + kk + j*8;
            float v[8];
#pragma unroll
            for (int q = 0; q < 8; q++) {
                int k = kk + j*8 + q;
                v[q] = fmaxf(0.f, fmaf(yp[q], s_sc[k], s_sh[k]));
            }
            uint4 h4, l4;
            split8(v, h4, l4);
            *(uint4*)(sm + SMB_H + so) = h4;
            *(uint4*)(sm + SMB_L + so) = l4;
        }
        __syncthreads();
#pragma unroll
        for (int kb = 0; kb < 4; kb++) {
            int chnk = kb*2 + (sub >> 1);
            uint32_t Ah[4][4], Al[4][4], Bh[4][2], Bl[4][2];
#pragma unroll
            for (int i = 0; i < 4; i++) {
                int row = wm*64 + i*16 + ((sub & 1) << 3) + rr;
                uint32_t so = (uint32_t)(row*128 + ((chnk ^ rr) << 4));
                LDSM4(Ah[i], smb + SMA_H + so);
                LDSM4(Al[i], smb + SMA_L + so);
            }
#pragma unroll
            for (int jj = 0; jj < 2; jj++) {
                int row = wn*32 + jj*16 + ((sub & 1) << 3) + rr;
                uint32_t so = (uint32_t)(row*128 + ((chnk ^ rr) << 4));
                uint32_t rg[4];
                LDSM4(rg, smb + SMB_H + so);
                Bh[jj*2][0] = rg[0]; Bh[jj*2+1][0] = rg[1];
                Bh[jj*2][1] = rg[2]; Bh[jj*2+1][1] = rg[3];
                LDSM4(rg, smb + SMB_L + so);
                Bl[jj*2][0] = rg[0]; Bl[jj*2+1][0] = rg[1];
                Bl[jj*2][1] = rg[2]; Bl[jj*2+1][1] = rg[3];
            }
#pragma unroll
            for (int i = 0; i < 4; i++)
#pragma unroll
                for (int jt = 0; jt < 4; jt++) {
                    mma_bf16(acc[i][jt], Ah[i], Bh[jt]);
                    mma_bf16(acc[i][jt], Ah[i], Bl[jt]);
                    mma_bf16(acc[i][jt], Al[i], Bh[jt]);
                }
        }
    }

#pragma unroll
    for (int i = 0; i < 4; i++) {
        int ch = wm*64 + i*16 + (lid >> 2);
        float b0v = bias[ch], b8v = bias[ch + 8];
#pragma unroll
        for (int jt = 0; jt < 4; jt++) {
            int ptl = wn*32 + jt*8 + (lid & 3)*2;
            int gp = p0 + ptl;
            int b = gp >> 13, n = gp & (Nq - 1);
            float2 v0 = make_float2(acc[i][jt][0] + b0v, acc[i][jt][1] + b0v);
            float2 v1 = make_float2(acc[i][jt][2] + b8v, acc[i][jt][3] + b8v);
            *(float2*)(out + ((size_t)b*CO1 + ch)*Nq + n)     = v0;
            *(float2*)(out + ((size_t)b*CO1 + ch + 8)*Nq + n) = v1;
        }
    }
}

// ---------------- per-channel BN stats (bn1 over d_out) -------------------------
__global__ __launch_bounds__(256) void stats_kernel(const float* __restrict__ Y,
    const float* __restrict__ g, const float* __restrict__ be,
    float* __restrict__ scale, float* __restrict__ shift,
    long long chan_stride, int nchunks, long long chunk_stride, int chunk_len, float inv_count)
{
    int o = blockIdx.x;
    int tid = threadIdx.x;
    float s = 0.f, q = 0.f;
    for (int cb = 0; cb < nchunks; cb++) {
        const float4* p = (const float4*)(Y + (size_t)o * chan_stride + (size_t)cb * chunk_stride);
        int len4 = chunk_len >> 2;
        for (int i = tid; i < len4; i += 256) {
            float4 v = p[i];
            s += (v.x + v.y) + (v.z + v.w);
            q += (v.x*v.x + v.y*v.y) + (v.z*v.z + v.w*v.w);
        }
    }
    __shared__ double ss[256], sq[256];
    ss[tid] = (double)s; sq[tid] = (double)q;
    __syncthreads();
    for (int st = 128; st > 0; st >>= 1) {
        if (tid < st) { ss[tid] += ss[tid+st]; sq[tid] += sq[tid+st]; }
        __syncthreads();
    }
    if (tid == 0) {
        double mean = ss[0] * (double)inv_count;
        double var  = sq[0] * (double)inv_count - mean*mean;
        double sc   = (double)g[o] / sqrt(var + 1e-5);
        scale[o] = (float)sc;
        shift[o] = (float)((double)be[o] - mean * sc);
    }
}

// ---------------- final BN + ReLU, in place on d_out ----------------------------
__global__ __launch_bounds__(256) void bnrelu_kernel(float* __restrict__ out)
{
    int i = blockIdx.x * 256 + threadIdx.x;
    int o = (i >> 11) & 127;
    float sc = g_scale1[o], sh = g_shift1[o];
    float4* p = (float4*)out;
    float4 v = p[i];
    v.x = fmaxf(0.f, fmaf(v.x, sc, sh));
    v.y = fmaxf(0.f, fmaf(v.y, sc, sh));
    v.z = fmaxf(0.f, fmaf(v.z, sc, sh));
    v.w = fmaxf(0.f, fmaf(v.w, sc, sh));
    p[i] = v;
}

// ---------------- launch ---------------------------------------------------------
extern "C" void kernel_launch(void* const* d_in, const int* in_sizes, int n_in,
                              void* d_out, int out_size)
{
    const float* xyz1    = (const float*)d_in[0];
    const float* xyz2    = (const float*)d_in[1];
    const float* norm1   = (const float*)d_in[2];
    const float* norm2   = (const float*)d_in[3];
    const float* points1 = (const float*)d_in[4];
    const float* points2 = (const float*)d_in[5];
    const float* W0      = (const float*)d_in[6];
    const float* b0      = (const float*)d_in[7];
    const float* g0      = (const float*)d_in[8];
    const float* be0     = (const float*)d_in[9];
    const float* W1      = (const float*)d_in[10];
    const float* b1      = (const float*)d_in[11];
    const float* g1      = (const float*)d_in[12];
    const float* be1     = (const float*)d_in[13];
    float* out = (float*)d_out;

    cudaFuncSetAttribute(gemm0_mma_kernel, cudaFuncAttributeMaxDynamicSharedMemorySize, G0_SMEM);
    cudaFuncSetAttribute(gemm1_mma_kernel, cudaFuncAttributeMaxDynamicSharedMemorySize, G1_SMEM);

    float *p2T_ptr, *sc1, *sh1;
    cudaGetSymbolAddress((void**)&p2T_ptr, g_p2T);
    cudaGetSymbolAddress((void**)&sc1, g_scale1);
    cudaGetSymbolAddress((void**)&sh1, g_shift1);

    // weight presplit (bf16 hi/lo)
    splitw_kernel<<<(CO0*CIN + CO1*CO0 + 255)/256, 256>>>(W0, W1);
    // points2 (B,256,2048) -> g_p2T (B,2048,256) fp32
    transpose_kernel<<<dim3(Mp/32, C2/32, Bsz), dim3(32,8)>>>(points2, p2T_ptr, C2, Mp, C2);
    // points1 -> split bf16 into g_Xhi/lo [col][256..383]
    transpose_split_kernel<<<dim3(Nq/32, C1/32, Bsz), dim3(32,8)>>>(points1);
    // 3-NN + interpolation -> g_Xhi/lo [col][0..255]
    knn_interp_kernel<<<dim3(Nq/KQ, Bsz), 512>>>(xyz1, xyz2, norm1, norm2);
    // conv0 (HMMA bf16x3) -> g_Y0T [pt][ch] + bn0 partials
    gemm0_mma_kernel<<<dim3(NC/128, CO0/128), 256, G0_SMEM>>>(b0);
    // bn0 affine
    reduce0_kernel<<<CO0, 256>>>(g0, be0);
    // conv1 (HMMA bf16x3, bn0+relu fused in staging) -> d_out raw
    gemm1_mma_kernel<<<dim3(NC/128), 256, G1_SMEM>>>(b1, out);
    // bn1 stats over d_out raw
    stats_kernel<<<CO1, 256>>>(out, g1, be1, sc1, sh1,
                               (long long)Nq, Bsz, (long long)(CO1*Nq), Nq, 1.0f/(float)NC);
    // final bn1 + relu in place
    bnrelu_kernel<<<(Bsz*CO1*Nq/4)/256, 256>>>(out);
}